// round 7
// baseline (speedup 1.0000x reference)
#include <cuda_runtime.h>
#include <cuda_bf16.h>
#include <mma.h>
#include <math.h>

using namespace nvcuda;

// Problem sizes (fixed for this problem instance)
#define B_ROWS 8192
#define DIMN   4096
#define PN     64

// ---------------------------------------------------------------------------
// Scratch (no cudaMalloc allowed -> __device__ globals)
// ---------------------------------------------------------------------------
__device__ float g_KQ[B_ROWS * 128];                 // 4 MB: [:, :64]=k dots, [:, 64:]=q dots
__device__ float g_V[(size_t)B_ROWS * DIMN];         // 128 MB: V, then normed (in-place LN)
__device__ float g_scale[B_ROWS];                    // per-row scalar c

// ---------------------------------------------------------------------------
// bf16x3 split-precision GEMM:  C[i,j] = sum_k A[i,k]*W[j,k] (+bias[j]) (+Xres[i,j])
// A: [M,K] row-major fp32, W: [N,K] row-major fp32 (NT gemm, K-contiguous).
// Each fp32 value is split: hi = bf16(x), lo = bf16(x - hi). Accumulate
// hi*hi + hi*lo + lo*hi in fp32 (lo*lo ~2^-17 dropped) -> near-fp32 accuracy.
// Tile: BM=128, BN=64, BK=32. 256 threads = 8 warps (4M x 2N), each warp does
// a 32x32 sub-tile with 2x2 m16n16k16 bf16 fragments, 3 MMAs per fragment pair.
// ---------------------------------------------------------------------------
constexpr int BM = 128, BN = 64, BK = 32;
constexpr int TSTR = 48;      // bf16 tile row stride (96B rows, 32B-aligned)
constexpr int CSTR = 72;      // fp32 C-staging stride
constexpr float PI_F = 3.14159265358979323846f;

// smem: bf16 tiles (As_hi|As_lo|Bs_hi|Bs_lo) = (128+128+64+64)*48*2B = 36864B
//       reused in epilogue as fp32 C staging 128*72*4B = 36864B
__global__ void __launch_bounds__(256)
gemm_bf16x3_kernel(const float* __restrict__ A, const float* __restrict__ W,
                   const float* __restrict__ bias, const float* __restrict__ Xres,
                   float* __restrict__ C, int K, int ldc)
{
    __shared__ __align__(32) char smem_raw[36864];
    __nv_bfloat16* As_hi = reinterpret_cast<__nv_bfloat16*>(smem_raw);
    __nv_bfloat16* As_lo = As_hi + BM * TSTR;            // +6144
    __nv_bfloat16* Bs_hi = As_lo + BM * TSTR;            // +12288
    __nv_bfloat16* Bs_lo = Bs_hi + BN * TSTR;            // +15360
    float* Cs = reinterpret_cast<float*>(smem_raw);

    const int tid = threadIdx.x;
    const int wid = tid >> 5;
    const int wm  = wid >> 1;           // 0..3 -> M offset wm*32
    const int wn  = wid & 1;            // 0..1 -> N offset wn*32
    const int bx  = blockIdx.x;
    const int by  = blockIdx.y;

    const float* Ag = A + (size_t)by * BM * K;
    const float* Wg = W + (size_t)bx * BN * K;

    wmma::fragment<wmma::accumulator, 16, 16, 16, float> acc[2][2];
#pragma unroll
    for (int i = 0; i < 2; ++i)
#pragma unroll
        for (int j = 0; j < 2; ++j)
            wmma::fill_fragment(acc[i][j], 0.0f);

    const int c4 = tid & 7;     // float4 column within BK=32
    const int r0 = tid >> 3;    // 0..31

    for (int k0 = 0; k0 < K; k0 += BK) {
        // ---- load + split A tile: 128 x 32 fp32 ----
#pragma unroll
        for (int p = 0; p < 4; ++p) {
            int m = r0 + p * 32;
            float4 f = *reinterpret_cast<const float4*>(Ag + (size_t)m * K + k0 + c4 * 4);
            __nv_bfloat16 hx = __float2bfloat16(f.x), hy = __float2bfloat16(f.y);
            __nv_bfloat16 hz = __float2bfloat16(f.z), hw = __float2bfloat16(f.w);
            int off = m * TSTR + c4 * 4;
            *reinterpret_cast<__nv_bfloat162*>(&As_hi[off])     = __nv_bfloat162(hx, hy);
            *reinterpret_cast<__nv_bfloat162*>(&As_hi[off + 2]) = __nv_bfloat162(hz, hw);
            *reinterpret_cast<__nv_bfloat162*>(&As_lo[off]) =
                __floats2bfloat162_rn(f.x - __bfloat162float(hx), f.y - __bfloat162float(hy));
            *reinterpret_cast<__nv_bfloat162*>(&As_lo[off + 2]) =
                __floats2bfloat162_rn(f.z - __bfloat162float(hz), f.w - __bfloat162float(hw));
        }
        // ---- load + split W tile: 64 x 32 fp32 ----
#pragma unroll
        for (int p = 0; p < 2; ++p) {
            int n = r0 + p * 32;
            float4 f = *reinterpret_cast<const float4*>(Wg + (size_t)n * K + k0 + c4 * 4);
            __nv_bfloat16 hx = __float2bfloat16(f.x), hy = __float2bfloat16(f.y);
            __nv_bfloat16 hz = __float2bfloat16(f.z), hw = __float2bfloat16(f.w);
            int off = n * TSTR + c4 * 4;
            *reinterpret_cast<__nv_bfloat162*>(&Bs_hi[off])     = __nv_bfloat162(hx, hy);
            *reinterpret_cast<__nv_bfloat162*>(&Bs_hi[off + 2]) = __nv_bfloat162(hz, hw);
            *reinterpret_cast<__nv_bfloat162*>(&Bs_lo[off]) =
                __floats2bfloat162_rn(f.x - __bfloat162float(hx), f.y - __bfloat162float(hy));
            *reinterpret_cast<__nv_bfloat162*>(&Bs_lo[off + 2]) =
                __floats2bfloat162_rn(f.z - __bfloat162float(hz), f.w - __bfloat162float(hw));
        }
        __syncthreads();

#pragma unroll
        for (int kk = 0; kk < BK; kk += 16) {
            wmma::fragment<wmma::matrix_a, 16, 16, 16, __nv_bfloat16, wmma::row_major> ah[2], al[2];
            wmma::fragment<wmma::matrix_b, 16, 16, 16, __nv_bfloat16, wmma::col_major> bh[2], bl[2];
#pragma unroll
            for (int i = 0; i < 2; ++i) {
                wmma::load_matrix_sync(ah[i], &As_hi[(wm * 32 + i * 16) * TSTR + kk], TSTR);
                wmma::load_matrix_sync(al[i], &As_lo[(wm * 32 + i * 16) * TSTR + kk], TSTR);
            }
#pragma unroll
            for (int j = 0; j < 2; ++j) {
                // col_major: element (k,n) at ptr[n*ldm + k] == Bs[n][k]
                wmma::load_matrix_sync(bh[j], &Bs_hi[(wn * 32 + j * 16) * TSTR + kk], TSTR);
                wmma::load_matrix_sync(bl[j], &Bs_lo[(wn * 32 + j * 16) * TSTR + kk], TSTR);
            }
#pragma unroll
            for (int i = 0; i < 2; ++i)
#pragma unroll
                for (int j = 0; j < 2; ++j) {
                    wmma::mma_sync(acc[i][j], ah[i], bh[j], acc[i][j]);
                    wmma::mma_sync(acc[i][j], ah[i], bl[j], acc[i][j]);
                    wmma::mma_sync(acc[i][j], al[i], bh[j], acc[i][j]);
                }
        }
        __syncthreads();
    }

    // ---- epilogue: stage C tile in smem (reuses tile region) ----
#pragma unroll
    for (int i = 0; i < 2; ++i)
#pragma unroll
        for (int j = 0; j < 2; ++j)
            wmma::store_matrix_sync(&Cs[(wm * 32 + i * 16) * CSTR + wn * 32 + j * 16],
                                    acc[i][j], CSTR, wmma::mem_row_major);
    __syncthreads();

    const int ce = tid & 15;   // 16 float4 across BN=64 cols
    const int re = tid >> 4;   // 0..15
#pragma unroll
    for (int p = 0; p < 8; ++p) {
        int rr = re + p * 16;
        float4 v = *reinterpret_cast<float4*>(&Cs[rr * CSTR + ce * 4]);
        int gcol = bx * BN + ce * 4;
        size_t cidx = (size_t)(by * BM + rr) * ldc + gcol;
        if (bias) {
            float4 bb = *reinterpret_cast<const float4*>(bias + gcol);
            v.x += bb.x; v.y += bb.y; v.z += bb.z; v.w += bb.w;
        }
        if (Xres) {
            float4 xv = *reinterpret_cast<const float4*>(Xres + cidx);
            v.x += xv.x; v.y += xv.y; v.z += xv.z; v.w += xv.w;
        }
        *reinterpret_cast<float4*>(C + cidx) = v;
    }
}

// ---------------------------------------------------------------------------
// Per-row scale: c = align_sum * softplus(align_sum/64 + 0.5) / 64
// KQ row layout: [0:64) = x.Wk[p]+bk, [64:128) = x.Wq[p]+bq
// One warp per row; 8 rows per 256-thread block.
// ---------------------------------------------------------------------------
__global__ void __launch_bounds__(256)
scale_kernel(const float* __restrict__ KQ, float* __restrict__ scale)
{
    int b = blockIdx.x * 8 + (threadIdx.x >> 5);
    int lane = threadIdx.x & 31;
    const float* row = KQ + (size_t)b * 128;

    float s = 0.f;
#pragma unroll
    for (int p = lane; p < PN; p += 32) {
        float tk = tanhf(row[p]);
        float tq = tanhf(row[64 + p]);
        s += cosf((tk - tq) * PI_F);
    }
#pragma unroll
    for (int o = 16; o; o >>= 1) s += __shfl_xor_sync(0xffffffffu, s, o);

    if (lane == 0) {
        float z = s * (1.0f / PN) + 0.5f;
        float gain = (z > 20.0f) ? z : log1pf(expf(z));   // softplus
        scale[b] = s * gain * (1.0f / PN);
    }
}

// ---------------------------------------------------------------------------
// Row LayerNorm of (c * V), in place: V <- (c*V - mu)*rsqrt(var+eps)*g + beta
// One block per row, 256 threads, 16 elements/thread via float4.
// ---------------------------------------------------------------------------
__global__ void __launch_bounds__(256)
ln_kernel(float* __restrict__ V, const float* __restrict__ scale,
          const float* __restrict__ gamma, const float* __restrict__ beta)
{
    const int b = blockIdx.x;
    const float c = scale[b];
    float* row = V + (size_t)b * DIMN;

    float4 v[4];
    float s = 0.f, ss = 0.f;
#pragma unroll
    for (int i = 0; i < 4; ++i) {
        v[i] = *reinterpret_cast<const float4*>(row + ((size_t)threadIdx.x + i * 256) * 4);
        v[i].x *= c; v[i].y *= c; v[i].z *= c; v[i].w *= c;
        s  += v[i].x + v[i].y + v[i].z + v[i].w;
        ss += v[i].x * v[i].x + v[i].y * v[i].y + v[i].z * v[i].z + v[i].w * v[i].w;
    }

    __shared__ float red[2][8];
    int lane = threadIdx.x & 31, w = threadIdx.x >> 5;
#pragma unroll
    for (int o = 16; o; o >>= 1) {
        s  += __shfl_xor_sync(0xffffffffu, s, o);
        ss += __shfl_xor_sync(0xffffffffu, ss, o);
    }
    if (lane == 0) { red[0][w] = s; red[1][w] = ss; }
    __syncthreads();
    if (threadIdx.x < 32) {
        s  = (lane < 8) ? red[0][lane] : 0.f;
        ss = (lane < 8) ? red[1][lane] : 0.f;
#pragma unroll
        for (int o = 4; o; o >>= 1) {
            s  += __shfl_xor_sync(0xffffffffu, s, o);
            ss += __shfl_xor_sync(0xffffffffu, ss, o);
        }
        if (lane == 0) { red[0][0] = s; red[1][0] = ss; }
    }
    __syncthreads();

    const float mean = red[0][0] * (1.0f / DIMN);
    const float var  = red[1][0] * (1.0f / DIMN) - mean * mean;
    const float rstd = rsqrtf(var + 1e-5f);

#pragma unroll
    for (int i = 0; i < 4; ++i) {
        int j4 = (threadIdx.x + i * 256) * 4;
        float4 gg = *reinterpret_cast<const float4*>(gamma + j4);
        float4 bb = *reinterpret_cast<const float4*>(beta + j4);
        float4 o;
        o.x = (v[i].x - mean) * rstd * gg.x + bb.x;
        o.y = (v[i].y - mean) * rstd * gg.y + bb.y;
        o.z = (v[i].z - mean) * rstd * gg.z + bb.z;
        o.w = (v[i].w - mean) * rstd * gg.w + bb.w;
        *reinterpret_cast<float4*>(row + j4) = o;
    }
}

// ---------------------------------------------------------------------------
// Launch
// ---------------------------------------------------------------------------
extern "C" void kernel_launch(void* const* d_in, const int* in_sizes, int n_in,
                              void* d_out, int out_size)
{
    const float* x    = (const float*)d_in[0];
    const float* Wk   = (const float*)d_in[1];
    const float* bk   = (const float*)d_in[2];
    const float* Wq   = (const float*)d_in[3];
    const float* bq   = (const float*)d_in[4];
    const float* Wv   = (const float*)d_in[5];
    const float* bv   = (const float*)d_in[6];
    const float* ln_g = (const float*)d_in[7];
    const float* ln_b = (const float*)d_in[8];
    const float* Wo   = (const float*)d_in[9];
    const float* bo   = (const float*)d_in[10];
    float* out = (float*)d_out;

    float *KQ, *V, *scale;
    cudaGetSymbolAddress((void**)&KQ,    g_KQ);
    cudaGetSymbolAddress((void**)&V,     g_V);
    cudaGetSymbolAddress((void**)&scale, g_scale);

    dim3 blk(256);

    // 1) phase GEMMs: KQ[:, :64] = x@Wk^T + bk ; KQ[:, 64:] = x@Wq^T + bq
    dim3 grid_kq(1, B_ROWS / BM);
    gemm_bf16x3_kernel<<<grid_kq, blk>>>(x, Wk, bk, nullptr, KQ,      DIMN, 128);
    gemm_bf16x3_kernel<<<grid_kq, blk>>>(x, Wq, bq, nullptr, KQ + 64, DIMN, 128);

    // 2) per-row resonance scale
    scale_kernel<<<B_ROWS / 8, blk>>>(KQ, scale);

    // 3) V = x@Wv^T + bv
    dim3 grid_big(DIMN / BN, B_ROWS / BM);
    gemm_bf16x3_kernel<<<grid_big, blk>>>(x, Wv, bv, nullptr, V, DIMN, DIMN);

    // 4) normed = LN(c*V)*g + b   (in place)
    ln_kernel<<<B_ROWS, blk>>>(V, scale, ln_g, ln_b);

    // 5) out = x + normed@Wo^T + bo
    gemm_bf16x3_kernel<<<grid_big, blk>>>(V, Wo, bo, x, out, DIMN, DIMN);
}

// round 8
// speedup vs baseline: 1.0017x; 1.0017x over previous
#include <cuda_runtime.h>
#include <cuda_bf16.h>
#include <mma.h>
#include <math.h>

using namespace nvcuda;

// Problem sizes (fixed for this problem instance)
#define B_ROWS 8192
#define DIMN   4096
#define PN     64

// ---------------------------------------------------------------------------
// Scratch (no cudaMalloc allowed -> __device__ globals)
// ---------------------------------------------------------------------------
__device__ float g_KQ[B_ROWS * 128];                 // 4 MB: [:, :64]=k dots, [:, 64:]=q dots
__device__ float g_V[(size_t)B_ROWS * DIMN];         // 128 MB: V, then normed (in-place LN)
__device__ float g_scale[B_ROWS];                    // per-row scalar c

// ---------------------------------------------------------------------------
// bf16x3 split-precision GEMM:  C[i,j] = sum_k A[i,k]*W[j,k] (+bias[j]) (+Xres[i,j])
// A: [M,K] row-major fp32, W: [N,K] row-major fp32 (NT gemm, K-contiguous).
// Each fp32 value is split: hi = bf16(x), lo = bf16(x - hi). Accumulate
// hi*hi + hi*lo + lo*hi in fp32 (lo*lo ~2^-17 dropped) -> near-fp32 accuracy.
// Tile: BM=128, BN=64, BK=32. 256 threads = 8 warps (4M x 2N), each warp does
// a 32x32 sub-tile with 2x2 m16n16k16 bf16 fragments, 3 MMAs per fragment pair.
// ---------------------------------------------------------------------------
constexpr int BM = 128, BN = 64, BK = 32;
constexpr int TSTR = 48;      // bf16 tile row stride (96B rows, 32B-aligned)
constexpr int CSTR = 72;      // fp32 C-staging stride
constexpr float PI_F = 3.14159265358979323846f;

// smem: bf16 tiles (As_hi|As_lo|Bs_hi|Bs_lo) = (128+128+64+64)*48*2B = 36864B
//       reused in epilogue as fp32 C staging 128*72*4B = 36864B
__global__ void __launch_bounds__(256)
gemm_bf16x3_kernel(const float* __restrict__ A, const float* __restrict__ W,
                   const float* __restrict__ bias, const float* __restrict__ Xres,
                   float* __restrict__ C, int K, int ldc)
{
    __shared__ __align__(32) char smem_raw[36864];
    __nv_bfloat16* As_hi = reinterpret_cast<__nv_bfloat16*>(smem_raw);
    __nv_bfloat16* As_lo = As_hi + BM * TSTR;            // +6144
    __nv_bfloat16* Bs_hi = As_lo + BM * TSTR;            // +12288
    __nv_bfloat16* Bs_lo = Bs_hi + BN * TSTR;            // +15360
    float* Cs = reinterpret_cast<float*>(smem_raw);

    const int tid = threadIdx.x;
    const int wid = tid >> 5;
    const int wm  = wid >> 1;           // 0..3 -> M offset wm*32
    const int wn  = wid & 1;            // 0..1 -> N offset wn*32
    const int bx  = blockIdx.x;
    const int by  = blockIdx.y;

    const float* Ag = A + (size_t)by * BM * K;
    const float* Wg = W + (size_t)bx * BN * K;

    wmma::fragment<wmma::accumulator, 16, 16, 16, float> acc[2][2];
#pragma unroll
    for (int i = 0; i < 2; ++i)
#pragma unroll
        for (int j = 0; j < 2; ++j)
            wmma::fill_fragment(acc[i][j], 0.0f);

    const int c4 = tid & 7;     // float4 column within BK=32
    const int r0 = tid >> 3;    // 0..31

    for (int k0 = 0; k0 < K; k0 += BK) {
        // ---- load + split A tile: 128 x 32 fp32 ----
#pragma unroll
        for (int p = 0; p < 4; ++p) {
            int m = r0 + p * 32;
            float4 f = *reinterpret_cast<const float4*>(Ag + (size_t)m * K + k0 + c4 * 4);
            __nv_bfloat16 hx = __float2bfloat16(f.x), hy = __float2bfloat16(f.y);
            __nv_bfloat16 hz = __float2bfloat16(f.z), hw = __float2bfloat16(f.w);
            int off = m * TSTR + c4 * 4;
            *reinterpret_cast<__nv_bfloat162*>(&As_hi[off])     = __nv_bfloat162(hx, hy);
            *reinterpret_cast<__nv_bfloat162*>(&As_hi[off + 2]) = __nv_bfloat162(hz, hw);
            *reinterpret_cast<__nv_bfloat162*>(&As_lo[off]) =
                __floats2bfloat162_rn(f.x - __bfloat162float(hx), f.y - __bfloat162float(hy));
            *reinterpret_cast<__nv_bfloat162*>(&As_lo[off + 2]) =
                __floats2bfloat162_rn(f.z - __bfloat162float(hz), f.w - __bfloat162float(hw));
        }
        // ---- load + split W tile: 64 x 32 fp32 ----
#pragma unroll
        for (int p = 0; p < 2; ++p) {
            int n = r0 + p * 32;
            float4 f = *reinterpret_cast<const float4*>(Wg + (size_t)n * K + k0 + c4 * 4);
            __nv_bfloat16 hx = __float2bfloat16(f.x), hy = __float2bfloat16(f.y);
            __nv_bfloat16 hz = __float2bfloat16(f.z), hw = __float2bfloat16(f.w);
            int off = n * TSTR + c4 * 4;
            *reinterpret_cast<__nv_bfloat162*>(&Bs_hi[off])     = __nv_bfloat162(hx, hy);
            *reinterpret_cast<__nv_bfloat162*>(&Bs_hi[off + 2]) = __nv_bfloat162(hz, hw);
            *reinterpret_cast<__nv_bfloat162*>(&Bs_lo[off]) =
                __floats2bfloat162_rn(f.x - __bfloat162float(hx), f.y - __bfloat162float(hy));
            *reinterpret_cast<__nv_bfloat162*>(&Bs_lo[off + 2]) =
                __floats2bfloat162_rn(f.z - __bfloat162float(hz), f.w - __bfloat162float(hw));
        }
        __syncthreads();

#pragma unroll
        for (int kk = 0; kk < BK; kk += 16) {
            wmma::fragment<wmma::matrix_a, 16, 16, 16, __nv_bfloat16, wmma::row_major> ah[2], al[2];
            wmma::fragment<wmma::matrix_b, 16, 16, 16, __nv_bfloat16, wmma::col_major> bh[2], bl[2];
#pragma unroll
            for (int i = 0; i < 2; ++i) {
                wmma::load_matrix_sync(ah[i], &As_hi[(wm * 32 + i * 16) * TSTR + kk], TSTR);
                wmma::load_matrix_sync(al[i], &As_lo[(wm * 32 + i * 16) * TSTR + kk], TSTR);
            }
#pragma unroll
            for (int j = 0; j < 2; ++j) {
                // col_major: element (k,n) at ptr[n*ldm + k] == Bs[n][k]
                wmma::load_matrix_sync(bh[j], &Bs_hi[(wn * 32 + j * 16) * TSTR + kk], TSTR);
                wmma::load_matrix_sync(bl[j], &Bs_lo[(wn * 32 + j * 16) * TSTR + kk], TSTR);
            }
#pragma unroll
            for (int i = 0; i < 2; ++i)
#pragma unroll
                for (int j = 0; j < 2; ++j) {
                    wmma::mma_sync(acc[i][j], ah[i], bh[j], acc[i][j]);
                    wmma::mma_sync(acc[i][j], ah[i], bl[j], acc[i][j]);
                    wmma::mma_sync(acc[i][j], al[i], bh[j], acc[i][j]);
                }
        }
        __syncthreads();
    }

    // ---- epilogue: stage C tile in smem (reuses tile region) ----
#pragma unroll
    for (int i = 0; i < 2; ++i)
#pragma unroll
        for (int j = 0; j < 2; ++j)
            wmma::store_matrix_sync(&Cs[(wm * 32 + i * 16) * CSTR + wn * 32 + j * 16],
                                    acc[i][j], CSTR, wmma::mem_row_major);
    __syncthreads();

    const int ce = tid & 15;   // 16 float4 across BN=64 cols
    const int re = tid >> 4;   // 0..15
#pragma unroll
    for (int p = 0; p < 8; ++p) {
        int rr = re + p * 16;
        float4 v = *reinterpret_cast<float4*>(&Cs[rr * CSTR + ce * 4]);
        int gcol = bx * BN + ce * 4;
        size_t cidx = (size_t)(by * BM + rr) * ldc + gcol;
        if (bias) {
            float4 bb = *reinterpret_cast<const float4*>(bias + gcol);
            v.x += bb.x; v.y += bb.y; v.z += bb.z; v.w += bb.w;
        }
        if (Xres) {
            float4 xv = *reinterpret_cast<const float4*>(Xres + cidx);
            v.x += xv.x; v.y += xv.y; v.z += xv.z; v.w += xv.w;
        }
        *reinterpret_cast<float4*>(C + cidx) = v;
    }
}

// ---------------------------------------------------------------------------
// Per-row scale: c = align_sum * softplus(align_sum/64 + 0.5) / 64
// KQ row layout: [0:64) = x.Wk[p]+bk, [64:128) = x.Wq[p]+bq
// One warp per row; 8 rows per 256-thread block.
// ---------------------------------------------------------------------------
__global__ void __launch_bounds__(256)
scale_kernel(const float* __restrict__ KQ, float* __restrict__ scale)
{
    int b = blockIdx.x * 8 + (threadIdx.x >> 5);
    int lane = threadIdx.x & 31;
    const float* row = KQ + (size_t)b * 128;

    float s = 0.f;
#pragma unroll
    for (int p = lane; p < PN; p += 32) {
        float tk = tanhf(row[p]);
        float tq = tanhf(row[64 + p]);
        s += cosf((tk - tq) * PI_F);
    }
#pragma unroll
    for (int o = 16; o; o >>= 1) s += __shfl_xor_sync(0xffffffffu, s, o);

    if (lane == 0) {
        float z = s * (1.0f / PN) + 0.5f;
        float gain = (z > 20.0f) ? z : log1pf(expf(z));   // softplus
        scale[b] = s * gain * (1.0f / PN);
    }
}

// ---------------------------------------------------------------------------
// Row LayerNorm of (c * V), in place: V <- (c*V - mu)*rsqrt(var+eps)*g + beta
// One block per row, 256 threads, 16 elements/thread via float4.
// ---------------------------------------------------------------------------
__global__ void __launch_bounds__(256)
ln_kernel(float* __restrict__ V, const float* __restrict__ scale,
          const float* __restrict__ gamma, const float* __restrict__ beta)
{
    const int b = blockIdx.x;
    const float c = scale[b];
    float* row = V + (size_t)b * DIMN;

    float4 v[4];
    float s = 0.f, ss = 0.f;
#pragma unroll
    for (int i = 0; i < 4; ++i) {
        v[i] = *reinterpret_cast<const float4*>(row + ((size_t)threadIdx.x + i * 256) * 4);
        v[i].x *= c; v[i].y *= c; v[i].z *= c; v[i].w *= c;
        s  += v[i].x + v[i].y + v[i].z + v[i].w;
        ss += v[i].x * v[i].x + v[i].y * v[i].y + v[i].z * v[i].z + v[i].w * v[i].w;
    }

    __shared__ float red[2][8];
    int lane = threadIdx.x & 31, w = threadIdx.x >> 5;
#pragma unroll
    for (int o = 16; o; o >>= 1) {
        s  += __shfl_xor_sync(0xffffffffu, s, o);
        ss += __shfl_xor_sync(0xffffffffu, ss, o);
    }
    if (lane == 0) { red[0][w] = s; red[1][w] = ss; }
    __syncthreads();
    if (threadIdx.x < 32) {
        s  = (lane < 8) ? red[0][lane] : 0.f;
        ss = (lane < 8) ? red[1][lane] : 0.f;
#pragma unroll
        for (int o = 4; o; o >>= 1) {
            s  += __shfl_xor_sync(0xffffffffu, s, o);
            ss += __shfl_xor_sync(0xffffffffu, ss, o);
        }
        if (lane == 0) { red[0][0] = s; red[1][0] = ss; }
    }
    __syncthreads();

    const float mean = red[0][0] * (1.0f / DIMN);
    const float var  = red[1][0] * (1.0f / DIMN) - mean * mean;
    const float rstd = rsqrtf(var + 1e-5f);

#pragma unroll
    for (int i = 0; i < 4; ++i) {
        int j4 = (threadIdx.x + i * 256) * 4;
        float4 gg = *reinterpret_cast<const float4*>(gamma + j4);
        float4 bb = *reinterpret_cast<const float4*>(beta + j4);
        float4 o;
        o.x = (v[i].x - mean) * rstd * gg.x + bb.x;
        o.y = (v[i].y - mean) * rstd * gg.y + bb.y;
        o.z = (v[i].z - mean) * rstd * gg.z + bb.z;
        o.w = (v[i].w - mean) * rstd * gg.w + bb.w;
        *reinterpret_cast<float4*>(row + j4) = o;
    }
}

// ---------------------------------------------------------------------------
// Launch
// ---------------------------------------------------------------------------
extern "C" void kernel_launch(void* const* d_in, const int* in_sizes, int n_in,
                              void* d_out, int out_size)
{
    const float* x    = (const float*)d_in[0];
    const float* Wk   = (const float*)d_in[1];
    const float* bk   = (const float*)d_in[2];
    const float* Wq   = (const float*)d_in[3];
    const float* bq   = (const float*)d_in[4];
    const float* Wv   = (const float*)d_in[5];
    const float* bv   = (const float*)d_in[6];
    const float* ln_g = (const float*)d_in[7];
    const float* ln_b = (const float*)d_in[8];
    const float* Wo   = (const float*)d_in[9];
    const float* bo   = (const float*)d_in[10];
    float* out = (float*)d_out;

    float *KQ, *V, *scale;
    cudaGetSymbolAddress((void**)&KQ,    g_KQ);
    cudaGetSymbolAddress((void**)&V,     g_V);
    cudaGetSymbolAddress((void**)&scale, g_scale);

    dim3 blk(256);

    // 1) phase GEMMs: KQ[:, :64] = x@Wk^T + bk ; KQ[:, 64:] = x@Wq^T + bq
    dim3 grid_kq(1, B_ROWS / BM);
    gemm_bf16x3_kernel<<<grid_kq, blk>>>(x, Wk, bk, nullptr, KQ,      DIMN, 128);
    gemm_bf16x3_kernel<<<grid_kq, blk>>>(x, Wq, bq, nullptr, KQ + 64, DIMN, 128);

    // 2) per-row resonance scale
    scale_kernel<<<B_ROWS / 8, blk>>>(KQ, scale);

    // 3) V = x@Wv^T + bv
    dim3 grid_big(DIMN / BN, B_ROWS / BM);
    gemm_bf16x3_kernel<<<grid_big, blk>>>(x, Wv, bv, nullptr, V, DIMN, DIMN);

    // 4) normed = LN(c*V)*g + b   (in place)
    ln_kernel<<<B_ROWS, blk>>>(V, scale, ln_g, ln_b);

    // 5) out = x + normed@Wo^T + bo
    gemm_bf16x3_kernel<<<grid_big, blk>>>(V, Wo, bo, x, out, DIMN, DIMN);
}

// round 11
// speedup vs baseline: 1.8361x; 1.8330x over previous
#include <cuda_runtime.h>
#include <cuda_bf16.h>
#include <cstdint>
#include <math.h>

// Problem sizes (fixed)
#define B_ROWS 8192
#define DIMN   4096
#define PN     64
constexpr float PI_F = 3.14159265358979323846f;

// ---------------------------------------------------------------------------
// Scratch (__device__ globals; no cudaMalloc allowed)
// ---------------------------------------------------------------------------
__device__ __nv_bfloat16 g_xhi[(size_t)B_ROWS * DIMN];   // 64 MB
__device__ __nv_bfloat16 g_xlo[(size_t)B_ROWS * DIMN];   // 64 MB
__device__ __nv_bfloat16 g_wvhi[(size_t)DIMN * DIMN];    // 32 MB
__device__ __nv_bfloat16 g_wvlo[(size_t)DIMN * DIMN];
__device__ __nv_bfloat16 g_wohi[(size_t)DIMN * DIMN];
__device__ __nv_bfloat16 g_wolo[(size_t)DIMN * DIMN];
__device__ __nv_bfloat16 g_kqwhi[128 * DIMN];            // 1 MB (Wk rows 0-63, Wq rows 64-127)
__device__ __nv_bfloat16 g_kqwlo[128 * DIMN];
__device__ __nv_bfloat16 g_nhi[(size_t)B_ROWS * DIMN];   // 64 MB (normed hi)
__device__ __nv_bfloat16 g_nlo[(size_t)B_ROWS * DIMN];
__device__ float g_KQ[(size_t)B_ROWS * 128];             // 4 MB
__device__ float g_V[(size_t)B_ROWS * DIMN];             // 128 MB
__device__ float g_scale[B_ROWS];
__device__ float g_bias128[128];

// ---------------------------------------------------------------------------
// PTX helpers (legacy tensor path: valid on plain sm_103 target)
// ---------------------------------------------------------------------------
__device__ __forceinline__ uint32_t smem_u32(const void* p) {
    uint32_t a;
    asm("{ .reg .u64 t; cvta.to.shared.u64 t, %1; cvt.u32.u64 %0, t; }" : "=r"(a) : "l"(p));
    return a;
}
__device__ __forceinline__ void cp16(uint32_t saddr, const void* g) {
    asm volatile("cp.async.cg.shared.global [%0], [%1], 16;" :: "r"(saddr), "l"(g));
}
#define CP_COMMIT() asm volatile("cp.async.commit_group;" ::: "memory")
#define CP_WAIT(n)  asm volatile("cp.async.wait_group %0;" :: "n"(n) : "memory")

__device__ __forceinline__ void ldsm_x4(uint32_t (&r)[4], uint32_t addr) {
    asm volatile("ldmatrix.sync.aligned.m8n8.x4.shared.b16 {%0,%1,%2,%3}, [%4];"
        : "=r"(r[0]), "=r"(r[1]), "=r"(r[2]), "=r"(r[3]) : "r"(addr));
}
__device__ __forceinline__ void mma_bf16(float (&d)[4], const uint32_t (&a)[4],
                                         uint32_t b0, uint32_t b1) {
    asm volatile("mma.sync.aligned.m16n8k16.row.col.f32.bf16.bf16.f32 "
        "{%0,%1,%2,%3}, {%4,%5,%6,%7}, {%8,%9}, {%0,%1,%2,%3};"
        : "+f"(d[0]), "+f"(d[1]), "+f"(d[2]), "+f"(d[3])
        : "r"(a[0]), "r"(a[1]), "r"(a[2]), "r"(a[3]), "r"(b0), "r"(b1));
}
__device__ __forceinline__ uint32_t swz(uint32_t off) { return off ^ ((off >> 3) & 0x70); }

// ---------------------------------------------------------------------------
// bf16x3 split GEMM via mma.sync:  C[i,j] = sum_k A[i,k]*W[j,k] (+bias) (+resid)
// A=(Ahi,Alo) [M,K], W=(Bhi,Blo) [N,K], both bf16 row-major K-contiguous.
// CTA tile 128x128x64, 256 thr = 8 warps (2M x 4N), warp tile 64x32.
// cp.async 2-stage double buffer; ldmatrix.x4 from SW128-swizzled smem.
// Products hi*hi + hi*lo + lo*hi accumulated in fp32 (lo*lo dropped, ~2^-17).
// ---------------------------------------------------------------------------
constexpr int BM = 128, BN = 128, BK = 64;
constexpr int OFF_AH = 0, OFF_AL = 16384, OFF_BH = 32768, OFF_BL = 49152;
constexpr int STAGE = 65536;
constexpr int DYN_SMEM = 2 * STAGE;   // 128 KB

__global__ void __launch_bounds__(256)
tc_gemm(const __nv_bfloat16* __restrict__ Ahi, const __nv_bfloat16* __restrict__ Alo,
        const __nv_bfloat16* __restrict__ Bhi, const __nv_bfloat16* __restrict__ Blo,
        const float* __restrict__ bias, const float* __restrict__ resid,
        float* __restrict__ C, int K, int ldc)
{
    extern __shared__ char dsm[];
    const uint32_t sb0 = smem_u32(dsm);

    const int tid  = threadIdx.x;
    const int wid  = tid >> 5;
    const int lane = tid & 31;
    const int warpM = wid >> 2;          // 0..1 -> M offset *64
    const int warpN = wid & 3;           // 0..3 -> N offset *32
    const int bx = blockIdx.x, by = blockIdx.y;

    const int r8 = tid >> 3;             // 0..31 (row group for cp.async)
    const int c8 = tid & 7;              // 16B chunk in 128B row
    const size_t arow0 = (size_t)(by * BM) * K;
    const size_t brow0 = (size_t)(bx * BN) * K;
    const uint32_t swst = swz((uint32_t)(r8 * 128 + c8 * 16));  // base swizzled chunk (rows +32p add 0x1000/0x2000.. no swizzle-bit overlap? rows bits>=7: +32 rows = +4096B, bits 12+, swizzle uses bits 7-9 of offset -> depends on row%8 only; r8 fixed low bits, +32 rows keeps row%8 -> swizzle mask identical; safe to add p*4096)

    // per-lane ldmatrix offsets (unswizzled byte offsets within a 16KB tile)
    const int rowA = lane & 15, ca = lane >> 4;
    uint32_t aoff[4];
#pragma unroll
    for (int mt = 0; mt < 4; ++mt)
        aoff[mt] = (uint32_t)((warpM * 64 + mt * 16 + rowA) * 128 + ca * 16);
    const int nrow = warpN * 32 + (lane & 7) + ((lane >> 4) & 1) * 8;
    const int kb   = ((lane >> 3) & 1) * 16;
    uint32_t boff[2];
#pragma unroll
    for (int p = 0; p < 2; ++p)
        boff[p] = (uint32_t)((nrow + p * 16) * 128 + kb);

    float acc[4][4][4];
#pragma unroll
    for (int i = 0; i < 4; ++i)
#pragma unroll
        for (int j = 0; j < 4; ++j)
#pragma unroll
            for (int e = 0; e < 4; ++e) acc[i][j][e] = 0.f;

    const int niter = K / BK;

    // ---- stage loader ----
    auto load_stage = [&](int it) {
        const uint32_t sb = sb0 + (uint32_t)(it & 1) * STAGE;
        const int k0 = it * BK;
        const size_t gofs = (size_t)k0 + c8 * 8;
#pragma unroll
        for (int p = 0; p < 4; ++p) {
            const int r = r8 + p * 32;
            const uint32_t sw = swst + p * 4096;
            const size_t ga = arow0 + (size_t)r * K + gofs;
            cp16(sb + OFF_AH + sw, Ahi + ga);
            cp16(sb + OFF_AL + sw, Alo + ga);
            const size_t gb = brow0 + (size_t)r * K + gofs;
            cp16(sb + OFF_BH + sw, Bhi + gb);
            cp16(sb + OFF_BL + sw, Blo + gb);
        }
    };

    load_stage(0);
    CP_COMMIT();

    for (int it = 0; it < niter; ++it) {
        if (it + 1 < niter) {
            load_stage(it + 1);
            CP_COMMIT();
            CP_WAIT(1);
        } else {
            CP_WAIT(0);
        }
        __syncthreads();

        const uint32_t sb = sb0 + (uint32_t)(it & 1) * STAGE;
#pragma unroll
        for (int kk = 0; kk < 4; ++kk) {
            uint32_t ah[4][4], al[4][4], bh[4][2], bl[4][2];
#pragma unroll
            for (int mt = 0; mt < 4; ++mt) {
                const uint32_t off = swz(aoff[mt] + kk * 32);
                ldsm_x4(ah[mt], sb + OFF_AH + off);
                ldsm_x4(al[mt], sb + OFF_AL + off);
            }
#pragma unroll
            for (int p = 0; p < 2; ++p) {
                const uint32_t off = swz(boff[p] + kk * 32);
                uint32_t r[4];
                ldsm_x4(r, sb + OFF_BH + off);
                bh[2*p][0] = r[0]; bh[2*p][1] = r[1];
                bh[2*p+1][0] = r[2]; bh[2*p+1][1] = r[3];
                ldsm_x4(r, sb + OFF_BL + off);
                bl[2*p][0] = r[0]; bl[2*p][1] = r[1];
                bl[2*p+1][0] = r[2]; bl[2*p+1][1] = r[3];
            }
            // 3 products; 16 independent accs between dependent MMAs
#pragma unroll
            for (int mt = 0; mt < 4; ++mt)
#pragma unroll
                for (int nt = 0; nt < 4; ++nt)
                    mma_bf16(acc[mt][nt], ah[mt], bh[nt][0], bh[nt][1]);
#pragma unroll
            for (int mt = 0; mt < 4; ++mt)
#pragma unroll
                for (int nt = 0; nt < 4; ++nt)
                    mma_bf16(acc[mt][nt], ah[mt], bl[nt][0], bl[nt][1]);
#pragma unroll
            for (int mt = 0; mt < 4; ++mt)
#pragma unroll
                for (int nt = 0; nt < 4; ++nt)
                    mma_bf16(acc[mt][nt], al[mt], bh[nt][0], bh[nt][1]);
        }
        __syncthreads();
    }

    // ---- epilogue: direct fp32 stores (float2 per reg pair) ----
    const int gr0 = by * BM + warpM * 64;
    const int gc0 = bx * BN + warpN * 32;
    const int lr = lane >> 2, lc = 2 * (lane & 3);
#pragma unroll
    for (int nt = 0; nt < 4; ++nt) {
        const int col = gc0 + nt * 8 + lc;
        const float2 bb = *reinterpret_cast<const float2*>(bias + col);
#pragma unroll
        for (int mt = 0; mt < 4; ++mt) {
            const int row = gr0 + mt * 16 + lr;
            const size_t o0 = (size_t)row * ldc + col;
            const size_t o1 = o0 + (size_t)8 * ldc;
            float2 v0 = { acc[mt][nt][0] + bb.x, acc[mt][nt][1] + bb.y };
            float2 v1 = { acc[mt][nt][2] + bb.x, acc[mt][nt][3] + bb.y };
            if (resid) {
                const float2 r0 = *reinterpret_cast<const float2*>(resid + o0);
                const float2 r1 = *reinterpret_cast<const float2*>(resid + o1);
                v0.x += r0.x; v0.y += r0.y; v1.x += r1.x; v1.y += r1.y;
            }
            *reinterpret_cast<float2*>(C + o0) = v0;
            *reinterpret_cast<float2*>(C + o1) = v1;
        }
    }
}

// ---------------------------------------------------------------------------
// Elementwise fp32 -> (bf16 hi, bf16 lo) split
// ---------------------------------------------------------------------------
__global__ void __launch_bounds__(256)
split_kernel(const float* __restrict__ src, __nv_bfloat16* __restrict__ hi,
             __nv_bfloat16* __restrict__ lo, int n4)
{
    int i = blockIdx.x * 256 + threadIdx.x;
    int stride = gridDim.x * 256;
    for (; i < n4; i += stride) {
        float4 f = reinterpret_cast<const float4*>(src)[i];
        __nv_bfloat16 hx = __float2bfloat16(f.x), hy = __float2bfloat16(f.y);
        __nv_bfloat16 hz = __float2bfloat16(f.z), hw = __float2bfloat16(f.w);
        reinterpret_cast<__nv_bfloat162*>(hi)[i * 2]     = __nv_bfloat162(hx, hy);
        reinterpret_cast<__nv_bfloat162*>(hi)[i * 2 + 1] = __nv_bfloat162(hz, hw);
        reinterpret_cast<__nv_bfloat162*>(lo)[i * 2] =
            __floats2bfloat162_rn(f.x - __bfloat162float(hx), f.y - __bfloat162float(hy));
        reinterpret_cast<__nv_bfloat162*>(lo)[i * 2 + 1] =
            __floats2bfloat162_rn(f.z - __bfloat162float(hz), f.w - __bfloat162float(hw));
    }
}

__global__ void concat_bias_kernel(const float* __restrict__ bk, const float* __restrict__ bq,
                                   float* __restrict__ b128)
{
    int t = threadIdx.x;
    if (t < 64) b128[t] = bk[t];
    else        b128[t] = bq[t - 64];
}

// ---------------------------------------------------------------------------
// Per-row scale: c = align_sum * softplus(align_sum/64 + 0.5) / 64
// ---------------------------------------------------------------------------
__global__ void __launch_bounds__(256)
scale_kernel(const float* __restrict__ KQ, float* __restrict__ scale)
{
    int b = blockIdx.x * 8 + (threadIdx.x >> 5);
    int lane = threadIdx.x & 31;
    const float* row = KQ + (size_t)b * 128;
    float s = 0.f;
#pragma unroll
    for (int p = lane; p < PN; p += 32) {
        float tk = tanhf(row[p]);
        float tq = tanhf(row[64 + p]);
        s += cosf((tk - tq) * PI_F);
    }
#pragma unroll
    for (int o = 16; o; o >>= 1) s += __shfl_xor_sync(0xffffffffu, s, o);
    if (lane == 0) {
        float z = s * (1.0f / PN) + 0.5f;
        float gain = (z > 20.0f) ? z : log1pf(expf(z));
        scale[b] = s * gain * (1.0f / PN);
    }
}

// ---------------------------------------------------------------------------
// LayerNorm of (c*V) -> split bf16 hi/lo outputs
// ---------------------------------------------------------------------------
__global__ void __launch_bounds__(256)
ln_split_kernel(const float* __restrict__ V, const float* __restrict__ scale,
                const float* __restrict__ gamma, const float* __restrict__ beta,
                __nv_bfloat16* __restrict__ nhi, __nv_bfloat16* __restrict__ nlo)
{
    const int b = blockIdx.x;
    const float c = scale[b];
    const float* row = V + (size_t)b * DIMN;

    float4 v[4];
    float s = 0.f, ss = 0.f;
#pragma unroll
    for (int i = 0; i < 4; ++i) {
        v[i] = *reinterpret_cast<const float4*>(row + ((size_t)threadIdx.x + i * 256) * 4);
        v[i].x *= c; v[i].y *= c; v[i].z *= c; v[i].w *= c;
        s  += v[i].x + v[i].y + v[i].z + v[i].w;
        ss += v[i].x * v[i].x + v[i].y * v[i].y + v[i].z * v[i].z + v[i].w * v[i].w;
    }
    __shared__ float red[2][8];
    int lane = threadIdx.x & 31, w = threadIdx.x >> 5;
#pragma unroll
    for (int o = 16; o; o >>= 1) {
        s  += __shfl_xor_sync(0xffffffffu, s, o);
        ss += __shfl_xor_sync(0xffffffffu, ss, o);
    }
    if (lane == 0) { red[0][w] = s; red[1][w] = ss; }
    __syncthreads();
    if (threadIdx.x < 32) {
        s  = (lane < 8) ? red[0][lane] : 0.f;
        ss = (lane < 8) ? red[1][lane] : 0.f;
#pragma unroll
        for (int o = 4; o; o >>= 1) {
            s  += __shfl_xor_sync(0xffffffffu, s, o);
            ss += __shfl_xor_sync(0xffffffffu, ss, o);
        }
        if (lane == 0) { red[0][0] = s; red[1][0] = ss; }
    }
    __syncthreads();
    const float mean = red[0][0] * (1.0f / DIMN);
    const float var  = red[1][0] * (1.0f / DIMN) - mean * mean;
    const float rstd = rsqrtf(var + 1e-5f);

    size_t rb = (size_t)b * DIMN;
#pragma unroll
    for (int i = 0; i < 4; ++i) {
        int j4 = (threadIdx.x + i * 256) * 4;
        float4 gg = *reinterpret_cast<const float4*>(gamma + j4);
        float4 bb = *reinterpret_cast<const float4*>(beta + j4);
        float ox = (v[i].x - mean) * rstd * gg.x + bb.x;
        float oy = (v[i].y - mean) * rstd * gg.y + bb.y;
        float oz = (v[i].z - mean) * rstd * gg.z + bb.z;
        float ow = (v[i].w - mean) * rstd * gg.w + bb.w;
        __nv_bfloat16 hx = __float2bfloat16(ox), hy = __float2bfloat16(oy);
        __nv_bfloat16 hz = __float2bfloat16(oz), hw = __float2bfloat16(ow);
        *reinterpret_cast<__nv_bfloat162*>(nhi + rb + j4)     = __nv_bfloat162(hx, hy);
        *reinterpret_cast<__nv_bfloat162*>(nhi + rb + j4 + 2) = __nv_bfloat162(hz, hw);
        *reinterpret_cast<__nv_bfloat162*>(nlo + rb + j4) =
            __floats2bfloat162_rn(ox - __bfloat162float(hx), oy - __bfloat162float(hy));
        *reinterpret_cast<__nv_bfloat162*>(nlo + rb + j4 + 2) =
            __floats2bfloat162_rn(oz - __bfloat162float(hz), ow - __bfloat162float(hw));
    }
}

// ---------------------------------------------------------------------------
// Launch
// ---------------------------------------------------------------------------
extern "C" void kernel_launch(void* const* d_in, const int* in_sizes, int n_in,
                              void* d_out, int out_size)
{
    const float* x    = (const float*)d_in[0];
    const float* Wk   = (const float*)d_in[1];
    const float* bk   = (const float*)d_in[2];
    const float* Wq   = (const float*)d_in[3];
    const float* bq   = (const float*)d_in[4];
    const float* Wv   = (const float*)d_in[5];
    const float* bv   = (const float*)d_in[6];
    const float* ln_g = (const float*)d_in[7];
    const float* ln_b = (const float*)d_in[8];
    const float* Wo   = (const float*)d_in[9];
    const float* bo   = (const float*)d_in[10];
    float* out = (float*)d_out;

    __nv_bfloat16 *xhi, *xlo, *wvhi, *wvlo, *wohi, *wolo, *kqwhi, *kqwlo, *nhi, *nlo;
    float *KQ, *V, *scale, *b128;
    cudaGetSymbolAddress((void**)&xhi,   g_xhi);
    cudaGetSymbolAddress((void**)&xlo,   g_xlo);
    cudaGetSymbolAddress((void**)&wvhi,  g_wvhi);
    cudaGetSymbolAddress((void**)&wvlo,  g_wvlo);
    cudaGetSymbolAddress((void**)&wohi,  g_wohi);
    cudaGetSymbolAddress((void**)&wolo,  g_wolo);
    cudaGetSymbolAddress((void**)&kqwhi, g_kqwhi);
    cudaGetSymbolAddress((void**)&kqwlo, g_kqwlo);
    cudaGetSymbolAddress((void**)&nhi,   g_nhi);
    cudaGetSymbolAddress((void**)&nlo,   g_nlo);
    cudaGetSymbolAddress((void**)&KQ,    g_KQ);
    cudaGetSymbolAddress((void**)&V,     g_V);
    cudaGetSymbolAddress((void**)&scale, g_scale);
    cudaGetSymbolAddress((void**)&b128,  g_bias128);

    cudaFuncSetAttribute(tc_gemm, cudaFuncAttributeMaxDynamicSharedMemorySize, DYN_SMEM);

    dim3 blk(256);
    const int SPLIT_GRID = 1184;

    // 0) splits
    split_kernel<<<SPLIT_GRID, blk>>>(x,  xhi,  xlo,  (B_ROWS * DIMN) / 4);
    split_kernel<<<SPLIT_GRID, blk>>>(Wv, wvhi, wvlo, (DIMN * DIMN) / 4);
    split_kernel<<<SPLIT_GRID, blk>>>(Wo, wohi, wolo, (DIMN * DIMN) / 4);
    split_kernel<<<128, blk>>>(Wk, kqwhi,             kqwlo,             (64 * DIMN) / 4);
    split_kernel<<<128, blk>>>(Wq, kqwhi + 64 * DIMN, kqwlo + 64 * DIMN, (64 * DIMN) / 4);
    concat_bias_kernel<<<1, 128>>>(bk, bq, b128);

    // 1) KQ = x @ [Wk;Wq]^T + [bk;bq]
    tc_gemm<<<dim3(1, B_ROWS / BM), blk, DYN_SMEM>>>(
        xhi, xlo, kqwhi, kqwlo, b128, nullptr, KQ, DIMN, 128);

    // 2) per-row resonance scale
    scale_kernel<<<B_ROWS / 8, blk>>>(KQ, scale);

    // 3) V = x @ Wv^T + bv
    tc_gemm<<<dim3(DIMN / BN, B_ROWS / BM), blk, DYN_SMEM>>>(
        xhi, xlo, wvhi, wvlo, bv, nullptr, V, DIMN, DIMN);

    // 4) normed = LN(c*V)*g + b  -> bf16 hi/lo
    ln_split_kernel<<<B_ROWS, blk>>>(V, scale, ln_g, ln_b, nhi, nlo);

    // 5) out = x + normed @ Wo^T + bo
    tc_gemm<<<dim3(DIMN / BN, B_ROWS / BM), blk, DYN_SMEM>>>(
        nhi, nlo, wohi, wolo, bo, x, out, DIMN, DIMN);
}

// round 12
// speedup vs baseline: 1.8694x; 1.0182x over previous
#include <cuda_runtime.h>
#include <cuda_bf16.h>
#include <cstdint>
#include <math.h>

// Problem sizes (fixed)
#define B_ROWS 8192
#define DIMN   4096
#define PN     64
constexpr float PI_F = 3.14159265358979323846f;

// N of merged GEMM1: [Wv(4096); Wk(64); Wq(64)]
constexpr int N1 = DIMN + 128;

// ---------------------------------------------------------------------------
// Scratch (__device__ globals; no cudaMalloc allowed)
// ---------------------------------------------------------------------------
__device__ __nv_bfloat16 g_xhi[(size_t)B_ROWS * DIMN];   // 64 MB
__device__ __nv_bfloat16 g_xlo[(size_t)B_ROWS * DIMN];   // 64 MB
__device__ __nv_bfloat16 g_w1hi[(size_t)N1 * DIMN];      // 33 MB  [Wv;Wk;Wq]
__device__ __nv_bfloat16 g_w1lo[(size_t)N1 * DIMN];
__device__ __nv_bfloat16 g_wohi[(size_t)DIMN * DIMN];    // 32 MB
__device__ __nv_bfloat16 g_wolo[(size_t)DIMN * DIMN];
__device__ __nv_bfloat16 g_nhi[(size_t)B_ROWS * DIMN];   // 64 MB (normed hi)
__device__ __nv_bfloat16 g_nlo[(size_t)B_ROWS * DIMN];
__device__ float g_KQ[(size_t)B_ROWS * 128];             // 4 MB
__device__ float g_V[(size_t)B_ROWS * DIMN];             // 128 MB
__device__ float g_b1[N1];                               // [bv;bk;bq]

// ---------------------------------------------------------------------------
// PTX helpers (legacy tensor path: valid on plain sm_103 target)
// ---------------------------------------------------------------------------
__device__ __forceinline__ uint32_t smem_u32(const void* p) {
    uint32_t a;
    asm("{ .reg .u64 t; cvta.to.shared.u64 t, %1; cvt.u32.u64 %0, t; }" : "=r"(a) : "l"(p));
    return a;
}
__device__ __forceinline__ void cp16(uint32_t saddr, const void* g) {
    asm volatile("cp.async.cg.shared.global [%0], [%1], 16;" :: "r"(saddr), "l"(g));
}
#define CP_COMMIT() asm volatile("cp.async.commit_group;" ::: "memory")
#define CP_WAIT(n)  asm volatile("cp.async.wait_group %0;" :: "n"(n) : "memory")

__device__ __forceinline__ void ldsm_x4(uint32_t (&r)[4], uint32_t addr) {
    asm volatile("ldmatrix.sync.aligned.m8n8.x4.shared.b16 {%0,%1,%2,%3}, [%4];"
        : "=r"(r[0]), "=r"(r[1]), "=r"(r[2]), "=r"(r[3]) : "r"(addr));
}
__device__ __forceinline__ void mma_bf16(float (&d)[4], const uint32_t (&a)[4],
                                         uint32_t b0, uint32_t b1) {
    asm volatile("mma.sync.aligned.m16n8k16.row.col.f32.bf16.bf16.f32 "
        "{%0,%1,%2,%3}, {%4,%5,%6,%7}, {%8,%9}, {%0,%1,%2,%3};"
        : "+f"(d[0]), "+f"(d[1]), "+f"(d[2]), "+f"(d[3])
        : "r"(a[0]), "r"(a[1]), "r"(a[2]), "r"(a[3]), "r"(b0), "r"(b1));
}
__device__ __forceinline__ uint32_t swz(uint32_t off) { return off ^ ((off >> 3) & 0x70); }

// ---------------------------------------------------------------------------
// bf16x3 split GEMM via mma.sync (3-stage cp.async pipeline, swizzled raster)
// C[i,j] = sum_k A[i,k]*W[j,k] (+bias[gcol]) (+resid)
// CTA tile 128x128x64; 256 thr = 8 warps (2M x 4N), warp tile 64x32.
// Grid: 1D, nbx*64 CTAs; GROUP=16 by-supertile rasterization for L2 reuse.
// Columns with bx >= bx_main are routed to Caux (ldc=128, col-4096): the
// folded [Wk;Wq] phase GEMM.
// ---------------------------------------------------------------------------
constexpr int BM = 128, BN = 128, BK = 64;
constexpr int OFF_AH = 0, OFF_AL = 16384, OFF_BH = 32768, OFF_BL = 49152;
constexpr int STAGE = 65536;
constexpr int STAGES = 3;
constexpr int DYN_SMEM = STAGES * STAGE;   // 192 KB
constexpr int GROUP = 16;

__global__ void __launch_bounds__(256)
tc_gemm(const __nv_bfloat16* __restrict__ Ahi, const __nv_bfloat16* __restrict__ Alo,
        const __nv_bfloat16* __restrict__ Bhi, const __nv_bfloat16* __restrict__ Blo,
        const float* __restrict__ bias, const float* __restrict__ resid,
        float* __restrict__ Cm, int ldcm, int bx_main, float* __restrict__ Caux,
        int K, int nbx)
{
    extern __shared__ char dsm[];
    const uint32_t sb0 = smem_u32(dsm);

    const int tid  = threadIdx.x;
    const int wid  = tid >> 5;
    const int lane = tid & 31;
    const int warpM = wid >> 2;
    const int warpN = wid & 3;

    // ---- supertile raster decode ----
    const int per = GROUP * nbx;
    const int g   = blockIdx.x / per;
    const int r_  = blockIdx.x - g * per;
    const int by  = g * GROUP + (r_ % GROUP);
    const int bx  = r_ / GROUP;

    const int r8 = tid >> 3;
    const int c8 = tid & 7;
    const size_t arow0 = (size_t)(by * BM) * K;
    const size_t brow0 = (size_t)(bx * BN) * K;
    const uint32_t swst = swz((uint32_t)(r8 * 128 + c8 * 16));

    // per-lane ldmatrix offsets (unswizzled byte offsets within a 16KB tile)
    const int rowA = lane & 15, ca = lane >> 4;
    uint32_t aoff[4];
#pragma unroll
    for (int mt = 0; mt < 4; ++mt)
        aoff[mt] = (uint32_t)((warpM * 64 + mt * 16 + rowA) * 128 + ca * 16);
    const int nrow = warpN * 32 + (lane & 7) + ((lane >> 4) & 1) * 8;
    const int kb   = ((lane >> 3) & 1) * 16;
    uint32_t boff[2];
#pragma unroll
    for (int p = 0; p < 2; ++p)
        boff[p] = (uint32_t)((nrow + p * 16) * 128 + kb);

    float acc[4][4][4];
#pragma unroll
    for (int i = 0; i < 4; ++i)
#pragma unroll
        for (int j = 0; j < 4; ++j)
#pragma unroll
            for (int e = 0; e < 4; ++e) acc[i][j][e] = 0.f;

    const int niter = K / BK;

    auto load_stage = [&](int it) {
        const uint32_t sb = sb0 + (uint32_t)(it % STAGES) * STAGE;
        const size_t gofs = (size_t)(it * BK) + c8 * 8;
#pragma unroll
        for (int p = 0; p < 4; ++p) {
            const int r = r8 + p * 32;
            const uint32_t sw = swst + p * 4096;
            const size_t ga = arow0 + (size_t)r * K + gofs;
            cp16(sb + OFF_AH + sw, Ahi + ga);
            cp16(sb + OFF_AL + sw, Alo + ga);
            const size_t gb = brow0 + (size_t)r * K + gofs;
            cp16(sb + OFF_BH + sw, Bhi + gb);
            cp16(sb + OFF_BL + sw, Blo + gb);
        }
    };

    // prologue: stages 0,1 in flight
    load_stage(0); CP_COMMIT();
    load_stage(1); CP_COMMIT();

    for (int it = 0; it < niter; ++it) {
        if (it + 1 < niter) { CP_WAIT(1); } else { CP_WAIT(0); }
        __syncthreads();                       // all warps done with stage it-1
        if (it + 2 < niter) { load_stage(it + 2); CP_COMMIT(); }  // writes (it+2)%3 != it%3,(it+1)%3

        const uint32_t sb = sb0 + (uint32_t)(it % STAGES) * STAGE;
#pragma unroll
        for (int kk = 0; kk < 4; ++kk) {
            uint32_t ah[4][4], al[4][4], bh[4][2], bl[4][2];
#pragma unroll
            for (int mt = 0; mt < 4; ++mt) {
                const uint32_t off = swz(aoff[mt] + kk * 32);
                ldsm_x4(ah[mt], sb + OFF_AH + off);
                ldsm_x4(al[mt], sb + OFF_AL + off);
            }
#pragma unroll
            for (int p = 0; p < 2; ++p) {
                const uint32_t off = swz(boff[p] + kk * 32);
                uint32_t r[4];
                ldsm_x4(r, sb + OFF_BH + off);
                bh[2*p][0] = r[0]; bh[2*p][1] = r[1];
                bh[2*p+1][0] = r[2]; bh[2*p+1][1] = r[3];
                ldsm_x4(r, sb + OFF_BL + off);
                bl[2*p][0] = r[0]; bl[2*p][1] = r[1];
                bl[2*p+1][0] = r[2]; bl[2*p+1][1] = r[3];
            }
#pragma unroll
            for (int mt = 0; mt < 4; ++mt)
#pragma unroll
                for (int nt = 0; nt < 4; ++nt)
                    mma_bf16(acc[mt][nt], ah[mt], bh[nt][0], bh[nt][1]);
#pragma unroll
            for (int mt = 0; mt < 4; ++mt)
#pragma unroll
                for (int nt = 0; nt < 4; ++nt)
                    mma_bf16(acc[mt][nt], ah[mt], bl[nt][0], bl[nt][1]);
#pragma unroll
            for (int mt = 0; mt < 4; ++mt)
#pragma unroll
                for (int nt = 0; nt < 4; ++nt)
                    mma_bf16(acc[mt][nt], al[mt], bh[nt][0], bh[nt][1]);
        }
    }
    // NOTE: no trailing sync needed; accumulators are in registers.

    // ---- epilogue ----
    const bool main_reg = (bx < bx_main);
    const int gr0 = by * BM + warpM * 64;
    const int gc0 = bx * BN + warpN * 32;
    const int lr = lane >> 2, lc = 2 * (lane & 3);
#pragma unroll
    for (int nt = 0; nt < 4; ++nt) {
        const int gcol = gc0 + nt * 8 + lc;
        const float2 bb = *reinterpret_cast<const float2*>(bias + gcol);
#pragma unroll
        for (int mt = 0; mt < 4; ++mt) {
            const int row = gr0 + mt * 16 + lr;
            float2 v0 = { acc[mt][nt][0] + bb.x, acc[mt][nt][1] + bb.y };
            float2 v1 = { acc[mt][nt][2] + bb.x, acc[mt][nt][3] + bb.y };
            if (main_reg) {
                const size_t o0 = (size_t)row * ldcm + gcol;
                const size_t o1 = o0 + (size_t)8 * ldcm;
                if (resid) {
                    const float2 r0 = *reinterpret_cast<const float2*>(resid + o0);
                    const float2 r1 = *reinterpret_cast<const float2*>(resid + o1);
                    v0.x += r0.x; v0.y += r0.y; v1.x += r1.x; v1.y += r1.y;
                }
                *reinterpret_cast<float2*>(Cm + o0) = v0;
                *reinterpret_cast<float2*>(Cm + o1) = v1;
            } else {
                const size_t o0 = (size_t)row * 128 + (gcol - DIMN);
                *reinterpret_cast<float2*>(Caux + o0) = v0;
                *reinterpret_cast<float2*>(Caux + o0 + 8 * 128) = v1;
            }
        }
    }
}

// ---------------------------------------------------------------------------
// Elementwise fp32 -> (bf16 hi, bf16 lo) split
// ---------------------------------------------------------------------------
__global__ void __launch_bounds__(256)
split_kernel(const float* __restrict__ src, __nv_bfloat16* __restrict__ hi,
             __nv_bfloat16* __restrict__ lo, int n4)
{
    int i = blockIdx.x * 256 + threadIdx.x;
    int stride = gridDim.x * 256;
    for (; i < n4; i += stride) {
        float4 f = reinterpret_cast<const float4*>(src)[i];
        __nv_bfloat16 hx = __float2bfloat16(f.x), hy = __float2bfloat16(f.y);
        __nv_bfloat16 hz = __float2bfloat16(f.z), hw = __float2bfloat16(f.w);
        reinterpret_cast<__nv_bfloat162*>(hi)[i * 2]     = __nv_bfloat162(hx, hy);
        reinterpret_cast<__nv_bfloat162*>(hi)[i * 2 + 1] = __nv_bfloat162(hz, hw);
        reinterpret_cast<__nv_bfloat162*>(lo)[i * 2] =
            __floats2bfloat162_rn(f.x - __bfloat162float(hx), f.y - __bfloat162float(hy));
        reinterpret_cast<__nv_bfloat162*>(lo)[i * 2 + 1] =
            __floats2bfloat162_rn(f.z - __bfloat162float(hz), f.w - __bfloat162float(hw));
    }
}

// concat bias: b1 = [bv(4096); bk(64); bq(64)]
__global__ void bias_concat_kernel(const float* __restrict__ bv, const float* __restrict__ bk,
                                   const float* __restrict__ bq, float* __restrict__ b1)
{
    int i = blockIdx.x * 256 + threadIdx.x;
    if (i >= N1) return;
    if (i < DIMN)            b1[i] = bv[i];
    else if (i < DIMN + 64)  b1[i] = bk[i - DIMN];
    else                     b1[i] = bq[i - DIMN - 64];
}

// ---------------------------------------------------------------------------
// Fused per-row scale + LayerNorm of (c*V) -> split bf16 hi/lo outputs
// c = align_sum * softplus(align_sum/64 + 0.5) / 64, from KQ row.
// ---------------------------------------------------------------------------
__global__ void __launch_bounds__(256)
ln_split_kernel(const float* __restrict__ V, const float* __restrict__ KQ,
                const float* __restrict__ gamma, const float* __restrict__ beta,
                __nv_bfloat16* __restrict__ nhi, __nv_bfloat16* __restrict__ nlo)
{
    const int b = blockIdx.x;
    const int tid = threadIdx.x;
    const int lane = tid & 31, w = tid >> 5;
    __shared__ float red[2][8];
    __shared__ float s_c;

    // --- per-row resonance scale from KQ (threads 0..63) ---
    float pa = 0.f;
    if (tid < 64) {
        float tk = tanhf(KQ[(size_t)b * 128 + tid]);
        float tq = tanhf(KQ[(size_t)b * 128 + 64 + tid]);
        pa = cosf((tk - tq) * PI_F);
    }
    if (w < 2) {
#pragma unroll
        for (int o = 16; o; o >>= 1) pa += __shfl_xor_sync(0xffffffffu, pa, o);
        if (lane == 0) red[0][w] = pa;
    }
    __syncthreads();
    if (tid == 0) {
        float asum = red[0][0] + red[0][1];
        float z = asum * (1.0f / PN) + 0.5f;
        float gain = (z > 20.0f) ? z : log1pf(expf(z));
        s_c = asum * gain * (1.0f / PN);
    }
    __syncthreads();
    const float c = s_c;

    // --- LayerNorm of c*V ---
    const float* row = V + (size_t)b * DIMN;
    float4 v[4];
    float s = 0.f, ss = 0.f;
#pragma unroll
    for (int i = 0; i < 4; ++i) {
        v[i] = *reinterpret_cast<const float4*>(row + ((size_t)tid + i * 256) * 4);
        v[i].x *= c; v[i].y *= c; v[i].z *= c; v[i].w *= c;
        s  += v[i].x + v[i].y + v[i].z + v[i].w;
        ss += v[i].x * v[i].x + v[i].y * v[i].y + v[i].z * v[i].z + v[i].w * v[i].w;
    }
#pragma unroll
    for (int o = 16; o; o >>= 1) {
        s  += __shfl_xor_sync(0xffffffffu, s, o);
        ss += __shfl_xor_sync(0xffffffffu, ss, o);
    }
    if (lane == 0) { red[0][w] = s; red[1][w] = ss; }
    __syncthreads();
    if (tid < 32) {
        s  = (lane < 8) ? red[0][lane] : 0.f;
        ss = (lane < 8) ? red[1][lane] : 0.f;
#pragma unroll
        for (int o = 4; o; o >>= 1) {
            s  += __shfl_xor_sync(0xffffffffu, s, o);
            ss += __shfl_xor_sync(0xffffffffu, ss, o);
        }
        if (lane == 0) { red[0][0] = s; red[1][0] = ss; }
    }
    __syncthreads();
    const float mean = red[0][0] * (1.0f / DIMN);
    const float var  = red[1][0] * (1.0f / DIMN) - mean * mean;
    const float rstd = rsqrtf(var + 1e-5f);

    size_t rb = (size_t)b * DIMN;
#pragma unroll
    for (int i = 0; i < 4; ++i) {
        int j4 = (tid + i * 256) * 4;
        float4 gg = *reinterpret_cast<const float4*>(gamma + j4);
        float4 bb = *reinterpret_cast<const float4*>(beta + j4);
        float ox = (v[i].x - mean) * rstd * gg.x + bb.x;
        float oy = (v[i].y - mean) * rstd * gg.y + bb.y;
        float oz = (v[i].z - mean) * rstd * gg.z + bb.z;
        float ow = (v[i].w - mean) * rstd * gg.w + bb.w;
        __nv_bfloat16 hx = __float2bfloat16(ox), hy = __float2bfloat16(oy);
        __nv_bfloat16 hz = __float2bfloat16(oz), hw = __float2bfloat16(ow);
        *reinterpret_cast<__nv_bfloat162*>(nhi + rb + j4)     = __nv_bfloat162(hx, hy);
        *reinterpret_cast<__nv_bfloat162*>(nhi + rb + j4 + 2) = __nv_bfloat162(hz, hw);
        *reinterpret_cast<__nv_bfloat162*>(nlo + rb + j4) =
            __floats2bfloat162_rn(ox - __bfloat162float(hx), oy - __bfloat162float(hy));
        *reinterpret_cast<__nv_bfloat162*>(nlo + rb + j4 + 2) =
            __floats2bfloat162_rn(oz - __bfloat162float(hz), ow - __bfloat162float(hw));
    }
}

// ---------------------------------------------------------------------------
// Launch
// ---------------------------------------------------------------------------
extern "C" void kernel_launch(void* const* d_in, const int* in_sizes, int n_in,
                              void* d_out, int out_size)
{
    const float* x    = (const float*)d_in[0];
    const float* Wk   = (const float*)d_in[1];
    const float* bk   = (const float*)d_in[2];
    const float* Wq   = (const float*)d_in[3];
    const float* bq   = (const float*)d_in[4];
    const float* Wv   = (const float*)d_in[5];
    const float* bv   = (const float*)d_in[6];
    const float* ln_g = (const float*)d_in[7];
    const float* ln_b = (const float*)d_in[8];
    const float* Wo   = (const float*)d_in[9];
    const float* bo   = (const float*)d_in[10];
    float* out = (float*)d_out;

    __nv_bfloat16 *xhi, *xlo, *w1hi, *w1lo, *wohi, *wolo, *nhi, *nlo;
    float *KQ, *V, *b1;
    cudaGetSymbolAddress((void**)&xhi,  g_xhi);
    cudaGetSymbolAddress((void**)&xlo,  g_xlo);
    cudaGetSymbolAddress((void**)&w1hi, g_w1hi);
    cudaGetSymbolAddress((void**)&w1lo, g_w1lo);
    cudaGetSymbolAddress((void**)&wohi, g_wohi);
    cudaGetSymbolAddress((void**)&wolo, g_wolo);
    cudaGetSymbolAddress((void**)&nhi,  g_nhi);
    cudaGetSymbolAddress((void**)&nlo,  g_nlo);
    cudaGetSymbolAddress((void**)&KQ,   g_KQ);
    cudaGetSymbolAddress((void**)&V,    g_V);
    cudaGetSymbolAddress((void**)&b1,   g_b1);

    cudaFuncSetAttribute(tc_gemm, cudaFuncAttributeMaxDynamicSharedMemorySize, DYN_SMEM);

    dim3 blk(256);
    const int SPLIT_GRID = 1184;

    // 0) splits: x; [Wv;Wk;Wq] -> w1; Wo -> wo; bias concat
    split_kernel<<<SPLIT_GRID, blk>>>(x,  xhi, xlo, (B_ROWS * DIMN) / 4);
    split_kernel<<<SPLIT_GRID, blk>>>(Wv, w1hi, w1lo, (DIMN * DIMN) / 4);
    split_kernel<<<128, blk>>>(Wk, w1hi + (size_t)DIMN * DIMN,
                                   w1lo + (size_t)DIMN * DIMN, (64 * DIMN) / 4);
    split_kernel<<<128, blk>>>(Wq, w1hi + (size_t)(DIMN + 64) * DIMN,
                                   w1lo + (size_t)(DIMN + 64) * DIMN, (64 * DIMN) / 4);
    split_kernel<<<SPLIT_GRID, blk>>>(Wo, wohi, wolo, (DIMN * DIMN) / 4);
    bias_concat_kernel<<<(N1 + 255) / 256, blk>>>(bv, bk, bq, b1);

    // 1) merged GEMM: [V | KQ] = x @ [Wv;Wk;Wq]^T + b1   (nbx=33, aux at bx=32)
    {
        const int nbx = N1 / BN;   // 33
        tc_gemm<<<nbx * (B_ROWS / BM), blk, DYN_SMEM>>>(
            xhi, xlo, w1hi, w1lo, b1, nullptr, V, DIMN, 32, KQ, DIMN, nbx);
    }

    // 2) fused scale + LN -> bf16 hi/lo
    ln_split_kernel<<<B_ROWS, blk>>>(V, KQ, ln_g, ln_b, nhi, nlo);

    // 3) out = x + normed @ Wo^T + bo
    {
        const int nbx = DIMN / BN; // 32
        tc_gemm<<<nbx * (B_ROWS / BM), blk, DYN_SMEM>>>(
            nhi, nlo, wohi, wolo, bo, x, out, DIMN, 32, nullptr, DIMN, nbx);
    }
}